// round 1
// baseline (speedup 1.0000x reference)
#include <cuda_runtime.h>
#include <cuda_bf16.h>
#include <cstdint>

#define SCALE_F 0.08838834764831845f

// ---------------- scratch (device globals; no allocation allowed) ----------------
__device__ __nv_bfloat16 g_Xb[4096 * 1024];          // X in bf16
__device__ __nv_bfloat16 g_Wb[24 * 1024 * 128];      // [Wq(8) | Wk(8) | Wv(8)] bf16
__device__ __nv_bfloat16 g_Qb[8 * 4096 * 128];       // Q bf16 [h][n][e]
__device__ __nv_bfloat16 g_Kb[8 * 4096 * 128];       // K bf16 [h][m][e]
__device__ float         g_Vf[8 * 4096 * 128];       // V f32  [h][m][e]
__device__ __nv_bfloat16 g_Vs[8 * 4096 * 128];       // V/colsum bf16
__device__ float         g_colsum[8 * 4096];         // sum_n exp(scale*q_n.k_m)

// ---------------- helpers ----------------
__device__ __forceinline__ uint32_t smem_u32(const void* p) {
    return (uint32_t)__cvta_generic_to_shared(p);
}

__device__ __forceinline__ void ldsm4(uint32_t a, uint32_t& r0, uint32_t& r1,
                                      uint32_t& r2, uint32_t& r3) {
    asm volatile("ldmatrix.sync.aligned.m8n8.x4.shared.b16 {%0,%1,%2,%3}, [%4];"
                 : "=r"(r0), "=r"(r1), "=r"(r2), "=r"(r3) : "r"(a));
}
__device__ __forceinline__ void ldsm4t(uint32_t a, uint32_t& r0, uint32_t& r1,
                                       uint32_t& r2, uint32_t& r3) {
    asm volatile("ldmatrix.sync.aligned.m8n8.x4.trans.shared.b16 {%0,%1,%2,%3}, [%4];"
                 : "=r"(r0), "=r"(r1), "=r"(r2), "=r"(r3) : "r"(a));
}

// mma.m16n8k16 row.col f32 += bf16*bf16
__device__ __forceinline__ void mma16816(float c[4], uint32_t a0, uint32_t a1,
                                         uint32_t a2, uint32_t a3,
                                         uint32_t b0, uint32_t b1) {
    asm volatile(
        "mma.sync.aligned.m16n8k16.row.col.f32.bf16.bf16.f32 "
        "{%0,%1,%2,%3},{%4,%5,%6,%7},{%8,%9},{%0,%1,%2,%3};"
        : "+f"(c[0]), "+f"(c[1]), "+f"(c[2]), "+f"(c[3])
        : "r"(a0), "r"(a1), "r"(a2), "r"(a3), "r"(b0), "r"(b1));
}

// Address patterns for ldmatrix x4 (lane -> row of one 8x8 matrix).
// Pattern A: matrices ordered (r0,c0),(r0+8,c0),(r0,c0+8),(r0+8,c0+8)
//   used for: A-frag (non-trans) from row-major [row][k] tile,
//             B-frag (trans)     from row-major [k][col] tile.
__device__ __forceinline__ uint32_t lm_addrA(uint32_t base, int ld, int row0, int col0, int lane) {
    int r = row0 + (lane & 7) + ((lane >> 3) & 1) * 8;
    int c = col0 + (lane >> 4) * 8;
    return base + (uint32_t)(r * ld + c) * 2u;
}
// Pattern B: matrices ordered (r0,c0),(r0,c0+8),(r0+8,c0),(r0+8,c0+8)
//   used for: B-frag (non-trans) from "n-major" tile (i.e. B^T stored row-major:
//             smem rows = output cols, smem cols = k).
__device__ __forceinline__ uint32_t lm_addrB(uint32_t base, int ld, int row0, int col0, int lane) {
    int r = row0 + (lane & 7) + (lane >> 4) * 8;
    int c = col0 + ((lane >> 3) & 1) * 8;
    return base + (uint32_t)(r * ld + c) * 2u;
}

__device__ __forceinline__ uint32_t pack_bf2(float lo, float hi) {
    __nv_bfloat162 p = __floats2bfloat162_rn(lo, hi);
    return *reinterpret_cast<uint32_t*>(&p);
}
__device__ __forceinline__ float sigmoidf_(float x) {
    return 1.0f / (1.0f + __expf(-x));
}

// ---------------- kernel 0: f32 -> bf16 conversions ----------------
__global__ void cvt_kernel(const float* __restrict__ X, const float* __restrict__ Wq,
                           const float* __restrict__ Wk, const float* __restrict__ Wv) {
    int stride = gridDim.x * blockDim.x;
    for (int i = blockIdx.x * blockDim.x + threadIdx.x; i < 4096 * 1024; i += stride)
        g_Xb[i] = __float2bfloat16(X[i]);
    for (int i = blockIdx.x * blockDim.x + threadIdx.x; i < 8 * 1024 * 128; i += stride) {
        g_Wb[i]               = __float2bfloat16(Wq[i]);
        g_Wb[1048576 + i]     = __float2bfloat16(Wk[i]);
        g_Wb[2097152 + i]     = __float2bfloat16(Wv[i]);
    }
}

// ---------------- kernel 1: batched projections ----------------
// grid (32 n-tiles, 24 gemms). C[n,e] = X[n,:] @ W_g[:,e] + bias_g[e]
#define PLD_A 40    // 32 + 8 pad (keeps ldmatrix 16B-aligned + conflict-free)
#define PLD_B 136   // 128 + 8 pad

__global__ __launch_bounds__(256) void proj_kernel(const float* __restrict__ bq,
                                                   const float* __restrict__ bk,
                                                   const float* __restrict__ bv) {
    __shared__ __nv_bfloat16 As[128 * PLD_A];
    __shared__ __nv_bfloat16 Bs[32 * PLD_B];
    const int g = blockIdx.y;           // 0..23
    const int n0 = blockIdx.x * 128;
    const int tid = threadIdx.x, lane = tid & 31, warp = tid >> 5;
    const __nv_bfloat16* Wg = g_Wb + g * (1024 * 128);
    const uint32_t sA = smem_u32(As), sB = smem_u32(Bs);

    float acc[16][4];
#pragma unroll
    for (int t = 0; t < 16; t++)
#pragma unroll
        for (int j = 0; j < 4; j++) acc[t][j] = 0.f;

    for (int k0 = 0; k0 < 1024; k0 += 32) {
#pragma unroll
        for (int i = 0; i < 4; i++) {            // A tile 128x32
            int idx = tid + 256 * i;
            int row = idx >> 3, cv = (idx & 7) * 4;
            *(uint2*)&As[row * PLD_A + cv] =
                *(const uint2*)&g_Xb[(n0 + row) * 1024 + k0 + cv];
        }
#pragma unroll
        for (int i = 0; i < 4; i++) {            // B tile 32x128
            int idx = tid + 256 * i;
            int row = idx >> 5, cv = (idx & 31) * 4;
            *(uint2*)&Bs[row * PLD_B + cv] =
                *(const uint2*)&Wg[(k0 + row) * 128 + cv];
        }
        __syncthreads();
#pragma unroll
        for (int kk = 0; kk < 32; kk += 16) {
            uint32_t a0, a1, a2, a3;
            ldsm4(lm_addrA(sA, PLD_A, warp * 16, kk, lane), a0, a1, a2, a3);
#pragma unroll
            for (int nt = 0; nt < 8; nt++) {
                uint32_t b0, b1, b2, b3;
                ldsm4t(lm_addrA(sB, PLD_B, kk, nt * 16, lane), b0, b1, b2, b3);
                mma16816(acc[2 * nt],     a0, a1, a2, a3, b0, b1);
                mma16816(acc[2 * nt + 1], a0, a1, a2, a3, b2, b3);
            }
        }
        __syncthreads();
    }

    const int h = g & 7, qkv = g >> 3;
    const float* bias = (qkv == 0 ? bq : qkv == 1 ? bk : bv) + h * 128;
#pragma unroll
    for (int t = 0; t < 16; t++) {
        int col = t * 8 + (lane & 3) * 2;
        int row = n0 + warp * 16 + (lane >> 2);
        float v0 = acc[t][0] + bias[col];
        float v1 = acc[t][1] + bias[col + 1];
        float v2 = acc[t][2] + bias[col];
        float v3 = acc[t][3] + bias[col + 1];
        int o0 = (h * 4096 + row) * 128 + col;
        int o1 = (h * 4096 + row + 8) * 128 + col;
        if (qkv == 0) {
            *(uint32_t*)&g_Qb[o0] = pack_bf2(v0, v1);
            *(uint32_t*)&g_Qb[o1] = pack_bf2(v2, v3);
        } else if (qkv == 1) {
            *(uint32_t*)&g_Kb[o0] = pack_bf2(v0, v1);
            *(uint32_t*)&g_Kb[o1] = pack_bf2(v2, v3);
        } else {
            *(float2*)&g_Vf[o0] = make_float2(v0, v1);
            *(float2*)&g_Vf[o1] = make_float2(v2, v3);
        }
    }
}

// ---------------- kernel 2: column sums of exp(score) ----------------
// S'[m][n] = K[m].Q[n]; colsum[m] = sum_n exp(SCALE * S')
// grid (32 m-tiles, 8 heads). smem: Ks[128][136] persistent, Qs[128][136] streamed.
__global__ __launch_bounds__(256) void colsum_kernel() {
    extern __shared__ __nv_bfloat16 smA[];
    __nv_bfloat16* Ks = smA;
    __nv_bfloat16* Qs = smA + 128 * 136;
    const int h = blockIdx.y, m0 = blockIdx.x * 128;
    const int tid = threadIdx.x, lane = tid & 31, warp = tid >> 5;
    const __nv_bfloat16* K = g_Kb + h * (4096 * 128);
    const __nv_bfloat16* Q = g_Qb + h * (4096 * 128);
    const uint32_t sK = smem_u32(Ks), sQ = smem_u32(Qs);

#pragma unroll
    for (int i = 0; i < 16; i++) {               // K tile 128x128 (persistent)
        int idx = tid + 256 * i;
        int row = idx >> 5, cv = (idx & 31) * 4;
        *(uint2*)&Ks[row * 136 + cv] = *(const uint2*)&K[(m0 + row) * 128 + cv];
    }

    float rs0 = 0.f, rs1 = 0.f;
    for (int n0 = 0; n0 < 4096; n0 += 128) {
        __syncthreads();
#pragma unroll
        for (int i = 0; i < 16; i++) {           // Q tile 128x128
            int idx = tid + 256 * i;
            int row = idx >> 5, cv = (idx & 31) * 4;
            *(uint2*)&Qs[row * 136 + cv] = *(const uint2*)&Q[(n0 + row) * 128 + cv];
        }
        __syncthreads();

        float sacc[16][4];
#pragma unroll
        for (int t = 0; t < 16; t++)
#pragma unroll
            for (int j = 0; j < 4; j++) sacc[t][j] = 0.f;

#pragma unroll
        for (int kk = 0; kk < 8; kk++) {
            uint32_t a0, a1, a2, a3;
            ldsm4(lm_addrA(sK, 136, warp * 16, kk * 16, lane), a0, a1, a2, a3);
#pragma unroll
            for (int nt = 0; nt < 8; nt++) {
                uint32_t b0, b1, b2, b3;
                ldsm4(lm_addrB(sQ, 136, nt * 16, kk * 16, lane), b0, b1, b2, b3);
                mma16816(sacc[2 * nt],     a0, a1, a2, a3, b0, b1);
                mma16816(sacc[2 * nt + 1], a0, a1, a2, a3, b2, b3);
            }
        }
#pragma unroll
        for (int t = 0; t < 16; t++) {
            rs0 += __expf(sacc[t][0] * SCALE_F) + __expf(sacc[t][1] * SCALE_F);
            rs1 += __expf(sacc[t][2] * SCALE_F) + __expf(sacc[t][3] * SCALE_F);
        }
    }
    rs0 += __shfl_xor_sync(0xffffffffu, rs0, 1);
    rs0 += __shfl_xor_sync(0xffffffffu, rs0, 2);
    rs1 += __shfl_xor_sync(0xffffffffu, rs1, 1);
    rs1 += __shfl_xor_sync(0xffffffffu, rs1, 2);
    if ((lane & 3) == 0) {
        int r = m0 + warp * 16 + (lane >> 2);
        g_colsum[h * 4096 + r]     = rs0;
        g_colsum[h * 4096 + r + 8] = rs1;
    }
}

// ---------------- kernel 3: fold 1/colsum into V ----------------
__global__ void scalev_kernel() {
    int stride = gridDim.x * blockDim.x;
    for (int i = blockIdx.x * blockDim.x + threadIdx.x; i < 8 * 4096 * 128; i += stride) {
        int hm = i >> 7;
        g_Vs[i] = __float2bfloat16(__fdividef(g_Vf[i], g_colsum[hm]));
    }
}

// ---------------- kernel 4: Z = exp(QK^T)*V', sigmoid ----------------
// grid (32 n-tiles, 8 heads).
__global__ __launch_bounds__(256, 1) void attn_kernel(float* __restrict__ out) {
    extern __shared__ __nv_bfloat16 smB[];
    __nv_bfloat16* Qs = smB;                  // 128x136 persistent
    __nv_bfloat16* Ks = smB + 128 * 136;      // streamed
    __nv_bfloat16* Vs = smB + 2 * 128 * 136;  // streamed
    const int h = blockIdx.y, n0 = blockIdx.x * 128;
    const int tid = threadIdx.x, lane = tid & 31, warp = tid >> 5;
    const __nv_bfloat16* Q = g_Qb + h * (4096 * 128);
    const __nv_bfloat16* K = g_Kb + h * (4096 * 128);
    const __nv_bfloat16* V = g_Vs + h * (4096 * 128);
    const uint32_t sQ = smem_u32(Qs), sK = smem_u32(Ks), sV = smem_u32(Vs);

#pragma unroll
    for (int i = 0; i < 16; i++) {               // Q tile (persistent)
        int idx = tid + 256 * i;
        int row = idx >> 5, cv = (idx & 31) * 4;
        *(uint2*)&Qs[row * 136 + cv] = *(const uint2*)&Q[(n0 + row) * 128 + cv];
    }

    float zacc[16][4];
#pragma unroll
    for (int t = 0; t < 16; t++)
#pragma unroll
        for (int j = 0; j < 4; j++) zacc[t][j] = 0.f;

    for (int m0 = 0; m0 < 4096; m0 += 128) {
        __syncthreads();
#pragma unroll
        for (int i = 0; i < 16; i++) {
            int idx = tid + 256 * i;
            int row = idx >> 5, cv = (idx & 31) * 4;
            *(uint2*)&Ks[row * 136 + cv] = *(const uint2*)&K[(m0 + row) * 128 + cv];
        }
#pragma unroll
        for (int i = 0; i < 16; i++) {
            int idx = tid + 256 * i;
            int row = idx >> 5, cv = (idx & 31) * 4;
            *(uint2*)&Vs[row * 136 + cv] = *(const uint2*)&V[(m0 + row) * 128 + cv];
        }
        __syncthreads();

        // S = Q K^T for this (n-tile, m-tile)
        float sacc[16][4];
#pragma unroll
        for (int t = 0; t < 16; t++)
#pragma unroll
            for (int j = 0; j < 4; j++) sacc[t][j] = 0.f;

#pragma unroll
        for (int kk = 0; kk < 8; kk++) {
            uint32_t a0, a1, a2, a3;
            ldsm4(lm_addrA(sQ, 136, warp * 16, kk * 16, lane), a0, a1, a2, a3);
#pragma unroll
            for (int nt = 0; nt < 8; nt++) {
                uint32_t b0, b1, b2, b3;
                ldsm4(lm_addrB(sK, 136, nt * 16, kk * 16, lane), b0, b1, b2, b3);
                mma16816(sacc[2 * nt],     a0, a1, a2, a3, b0, b1);
                mma16816(sacc[2 * nt + 1], a0, a1, a2, a3, b2, b3);
            }
        }

        // P = exp(SCALE*S) packed into A-fragments (C-frag layout == A-frag layout)
        uint32_t pf[8][4];
#pragma unroll
        for (int j = 0; j < 8; j++) {
            pf[j][0] = pack_bf2(__expf(sacc[2 * j][0] * SCALE_F),
                                __expf(sacc[2 * j][1] * SCALE_F));
            pf[j][1] = pack_bf2(__expf(sacc[2 * j][2] * SCALE_F),
                                __expf(sacc[2 * j][3] * SCALE_F));
            pf[j][2] = pack_bf2(__expf(sacc[2 * j + 1][0] * SCALE_F),
                                __expf(sacc[2 * j + 1][1] * SCALE_F));
            pf[j][3] = pack_bf2(__expf(sacc[2 * j + 1][2] * SCALE_F),
                                __expf(sacc[2 * j + 1][3] * SCALE_F));
        }

        // Z += P @ V'  (k = m dimension)
#pragma unroll
        for (int j = 0; j < 8; j++) {
#pragma unroll
            for (int et = 0; et < 8; et++) {
                uint32_t b0, b1, b2, b3;
                ldsm4t(lm_addrA(sV, 136, j * 16, et * 16, lane), b0, b1, b2, b3);
                mma16816(zacc[2 * et],     pf[j][0], pf[j][1], pf[j][2], pf[j][3], b0, b1);
                mma16816(zacc[2 * et + 1], pf[j][0], pf[j][1], pf[j][2], pf[j][3], b2, b3);
            }
        }
    }

    // epilogue: sigmoid, write out[n][h*128+e]
#pragma unroll
    for (int t = 0; t < 16; t++) {
        int col = h * 128 + t * 8 + (lane & 3) * 2;
        int row = n0 + warp * 16 + (lane >> 2);
        *(float2*)&out[row * 1024 + col] =
            make_float2(sigmoidf_(zacc[t][0]), sigmoidf_(zacc[t][1]));
        *(float2*)&out[(row + 8) * 1024 + col] =
            make_float2(sigmoidf_(zacc[t][2]), sigmoidf_(zacc[t][3]));
    }
}

// ---------------- launch ----------------
extern "C" void kernel_launch(void* const* d_in, const int* in_sizes, int n_in,
                              void* d_out, int out_size) {
    const float* X  = (const float*)d_in[0];
    const float* Wq = (const float*)d_in[1];
    const float* bq = (const float*)d_in[2];
    const float* Wk = (const float*)d_in[3];
    const float* bk = (const float*)d_in[4];
    const float* Wv = (const float*)d_in[5];
    const float* bv = (const float*)d_in[6];
    float* out = (float*)d_out;

    cudaFuncSetAttribute(colsum_kernel, cudaFuncAttributeMaxDynamicSharedMemorySize,
                         2 * 128 * 136 * 2);
    cudaFuncSetAttribute(attn_kernel, cudaFuncAttributeMaxDynamicSharedMemorySize,
                         3 * 128 * 136 * 2);

    cvt_kernel<<<2048, 256>>>(X, Wq, Wk, Wv);
    proj_kernel<<<dim3(32, 24), 256>>>(bq, bk, bv);
    colsum_kernel<<<dim3(32, 8), 256, 2 * 128 * 136 * 2>>>();
    scalev_kernel<<<2048, 256>>>();
    attn_kernel<<<dim3(32, 8), 256, 3 * 128 * 136 * 2>>>(out);
}